// round 15
// baseline (speedup 1.0000x reference)
#include <cuda_runtime.h>
#include <cuda_fp16.h>
#include <cstdint>
#include <math.h>

// Shapes (fixed)
#define B_ 8
#define S_ 1024
#define D_ 1024
#define H_ 16
#define DK_ 64
#define F_ 4096
#define MROWS (B_ * S_)          // 8192
#define QKV_N (3 * D_)           // 3072
#define QK_N 2048

#define QSCALE 0.18033688f       // 0.125 * log2(e), folded into q

// ================= scratch (device globals; no allocations allowed) =================
__device__ float g_bqkv[QKV_N];
// fp16 activations
__device__ __half g_src_h [MROWS * D_];
__device__ __half g_qkh   [MROWS * QK_N];        // q|k fp16, head-major per section
__device__ __half g_vt    [B_ * H_ * DK_ * S_];  // V^T per (b,h): [dk][s]
__device__ __half g_att_h [MROWS * D_];
__device__ __half g_proj_h[MROWS * D_];
__device__ __half g_x_h   [MROWS * D_];
__device__ __half g_ffh_h [MROWS * F_];
__device__ __half g_ff_h  [MROWS * D_];
// pre-transposed fp16 weights, [N][K] row-major (B operands)
__device__ __half g_Bqkv[QKV_N * D_];
__device__ __half g_Bo  [D_ * D_];
__device__ __half g_B1  [F_ * D_];
__device__ __half g_B2  [D_ * F_];

// ================= helpers =================
__device__ __forceinline__ uint32_t smem_u32(const void* p) {
    uint32_t a;
    asm("{ .reg .u64 t; cvta.to.shared.u64 t, %1; cvt.u32.u64 %0, t; }" : "=r"(a) : "l"(p));
    return a;
}
__device__ __forceinline__ void cp16(uint32_t s, const void* g) {
    asm volatile("cp.async.cg.shared.global [%0], [%1], 16;" :: "r"(s), "l"(g));
}
#define CP_COMMIT() asm volatile("cp.async.commit_group;" ::: "memory")
#define CP_WAIT(n)  asm volatile("cp.async.wait_group %0;" :: "n"(n) : "memory")

#define LDM4(r, a) \
    asm volatile("ldmatrix.sync.aligned.m8n8.x4.shared.b16 {%0,%1,%2,%3}, [%4];" \
        : "=r"((r)[0]), "=r"((r)[1]), "=r"((r)[2]), "=r"((r)[3]) : "r"(a))

__device__ __forceinline__ void mma16816(float* c, const uint32_t* a, uint32_t b0, uint32_t b1) {
    asm volatile("mma.sync.aligned.m16n8k16.row.col.f32.f16.f16.f32 "
                 "{%0,%1,%2,%3}, {%4,%5,%6,%7}, {%8,%9}, {%0,%1,%2,%3};"
                 : "+f"(c[0]), "+f"(c[1]), "+f"(c[2]), "+f"(c[3])
                 : "r"(a[0]), "r"(a[1]), "r"(a[2]), "r"(a[3]), "r"(b0), "r"(b1));
}
__device__ __forceinline__ uint32_t pack_h2(float x, float y) {
    __half2 h = __floats2half2_rn(x, y);
    return *(uint32_t*)&h;
}
__device__ __forceinline__ uint32_t ex2_h2(uint32_t x) {
    uint32_t d;
    asm("ex2.approx.f16x2 %0, %1;" : "=r"(d) : "r"(x));
    return d;
}

// ================= fused pre-pass: all weight transposes + src fp16 + bias pack =================
__global__ void __launch_bounds__(256) prepass_kernel(
    const float* __restrict__ src,
    const float* __restrict__ Wq, const float* __restrict__ Wk, const float* __restrict__ Wv,
    const float* __restrict__ Wo, const float* __restrict__ W1, const float* __restrict__ W2,
    const float* __restrict__ bq, const float* __restrict__ bk, const float* __restrict__ bv,
    __half* __restrict__ sh, __half* __restrict__ Bq_, __half* __restrict__ Bo_,
    __half* __restrict__ B1_, __half* __restrict__ B2_)
{
    __shared__ float t[32][33];
    int x = threadIdx.x, y = threadIdx.y;
    int bid = blockIdx.x;

    const float* in; __half* oh;
    int C, opitch, r0, c0, orow0;

    if (bid < 3072) {                     // Wq/Wk/Wv: [H,1024,64] -> Bq rows sec*1024+h*64+dk
        int seg = bid >> 10;
        int local = bid & 1023;
        int bx = local & 1;
        int by = (local >> 1) & 31;
        int bz = local >> 6;
        const float* W = (seg == 0) ? Wq : (seg == 1) ? Wk : Wv;
        in = W + (size_t)bz * (1024 * 64);
        C = 64; oh = Bq_; opitch = 1024;
        r0 = by * 32; c0 = bx * 32;
        orow0 = seg * 1024 + bz * 64 + c0;
    } else if (bid < 4096) {              // Wo [1024,1024]
        int local = bid - 3072;
        int bx = local & 31, by = local >> 5;
        in = Wo; C = 1024; oh = Bo_; opitch = 1024;
        r0 = by * 32; c0 = bx * 32; orow0 = c0;
    } else if (bid < 8192) {              // W1 [1024,4096]
        int local = bid - 4096;
        int bx = local & 127, by = local >> 7;
        in = W1; C = 4096; oh = B1_; opitch = 1024;
        r0 = by * 32; c0 = bx * 32; orow0 = c0;
    } else if (bid < 12288) {             // W2 [4096,1024]
        int local = bid - 8192;
        int bx = local & 31, by = local >> 5;
        in = W2; C = 1024; oh = B2_; opitch = 4096;
        r0 = by * 32; c0 = bx * 32; orow0 = c0;
    } else if (bid < 20480) {             // src f32 -> fp16
        int local = bid - 12288;
        int tid = y * 32 + x;
        size_t i = ((size_t)local * 256 + tid) << 2;
        float4 v = *(const float4*)(src + i);
        *(__half2*)(sh + i)     = __floats2half2_rn(v.x, v.y);
        *(__half2*)(sh + i + 2) = __floats2half2_rn(v.z, v.w);
        return;
    } else {                              // bias pack
        int local = bid - 20480;
        int tid = y * 32 + x;
        int n = local * 256 + tid;
        if (n < QKV_N) {
            int sec = n >> 10, r = n & 1023;
            const float* bb = (sec == 0) ? bq : (sec == 1) ? bk : bv;
            g_bqkv[n] = bb[r];
        }
        return;
    }

#pragma unroll
    for (int i = 0; i < 4; i++)
        t[y + i * 8][x] = in[(size_t)(r0 + y + i * 8) * C + c0 + x];
    __syncthreads();
#pragma unroll
    for (int i = 0; i < 4; i++)
        oh[(size_t)(orow0 + y + i * 8) * opitch + r0 + x] = __float2half_rn(t[x][y + i * 8]);
}
#define PREPASS_BLOCKS 20492

// ================= mma.sync fp16 GEMM (static 128x128, 128 thr, 64x64 warp tile) =================
// vtmode=1: C[m][n] scattered to vt[(b*16+h)*64+dk][s] (m=h*64+dk, n=b*1024+s), bias per-ROW.
#define ROWB 144
#define HALF_STAGE (128 * ROWB)
#define STAGE_B (2 * HALF_STAGE)
#define GEMM_SMEM (2 * STAGE_B)

__device__ __forceinline__ void gload(uint32_t sb,
    const __half* __restrict__ A, const __half* __restrict__ Bw,
    int K, int k0, int tid)
{
#pragma unroll
    for (int g = 0; g < 16; g++) {
        int item = tid + (g << 7);
        int r = item >> 3;
        int ch = (item & 7) << 4;
        if (r < 128)
            cp16(sb + r * ROWB + ch, A + (size_t)r * K + k0 + (ch >> 1));
        else
            cp16(sb + HALF_STAGE + (r - 128) * ROWB + ch,
                 Bw + (size_t)(r - 128) * K + k0 + (ch >> 1));
    }
}

__global__ void __launch_bounds__(128, 2) mma_gemm_kernel(
    const __half* __restrict__ A, const __half* __restrict__ Bw,
    const float* __restrict__ bias,
    __half* __restrict__ Ch,
    int N, int K, int doRelu, int qcols, int vtmode)
{
    extern __shared__ char sm[];
    uint32_t sb = smem_u32(sm);
    int tid = threadIdx.x, wid = tid >> 5, lane = tid & 31;
    int bm = blockIdx.y << 7, bn = blockIdx.x << 7;
    A  += (size_t)bm * K;
    Bw += (size_t)bn * K;

    float acc[4][8][4];
#pragma unroll
    for (int mt = 0; mt < 4; mt++)
#pragma unroll
        for (int nt = 0; nt < 8; nt++)
#pragma unroll
            for (int r = 0; r < 4; r++) acc[mt][nt][r] = 0.f;

    int wm = (wid >> 1) << 6;
    int wn = (wid & 1) << 6;
    int lr = lane & 15;
    int lk = (lane >> 4) << 4;

    int niter = K >> 6;
    gload(sb, A, Bw, K, 0, tid);
    CP_COMMIT();

    for (int it = 0; it < niter; it++) {
        if (it + 1 < niter) {
            gload(sb + ((it + 1) & 1) * STAGE_B, A, Bw, K, (it + 1) << 6, tid);
            CP_COMMIT();
            CP_WAIT(1);
        } else {
            CP_WAIT(0);
        }
        __syncthreads();

        uint32_t stage = sb + (it & 1) * STAGE_B;
        uint32_t ab = stage + (wm + lr) * ROWB + lk;
        uint32_t bb = stage + HALF_STAGE + (wn + lr) * ROWB + lk;
#pragma unroll
        for (int j = 0; j < 4; j++) {
            uint32_t ko = j << 5;
            uint32_t bf[4][4];
#pragma unroll
            for (int nb = 0; nb < 4; nb++)
                LDM4(bf[nb], bb + nb * 16 * ROWB + ko);
#pragma unroll
            for (int mt = 0; mt < 4; mt++) {
                uint32_t af[4];
                LDM4(af, ab + mt * 16 * ROWB + ko);
#pragma unroll
                for (int nb = 0; nb < 4; nb++) {
                    mma16816(acc[mt][2 * nb],     af, bf[nb][0], bf[nb][2]);
                    mma16816(acc[mt][2 * nb + 1], af, bf[nb][1], bf[nb][3]);
                }
            }
        }
        __syncthreads();
    }

    int orow = bm + wm + (lane >> 2);
    int ocol = bn + wn + ((lane & 3) << 1);

    if (vtmode) {
        // V^T scatter epilogue: bias per row; write vt[(b*16+h)*64+dk][s]
#pragma unroll
        for (int mt = 0; mt < 4; mt++) {
            int r0 = orow + mt * 16;
            float bi0 = bias[r0], bi8 = bias[r0 + 8];
            int h0 = r0 >> 6, dk0 = r0 & 63;
            int h8 = (r0 + 8) >> 6, dk8 = (r0 + 8) & 63;
#pragma unroll
            for (int nt = 0; nt < 8; nt++) {
                int c = ocol + nt * 8;
                int b = c >> 10, s = c & 1023;
                size_t o0 = ((size_t)((b * 16 + h0) * 64 + dk0)) * 1024 + s;
                size_t o8 = ((size_t)((b * 16 + h8) * 64 + dk8)) * 1024 + s;
                *(__half2*)(Ch + o0) = __floats2half2_rn(acc[mt][nt][0] + bi0,
                                                         acc[mt][nt][1] + bi0);
                *(__half2*)(Ch + o8) = __floats2half2_rn(acc[mt][nt][2] + bi8,
                                                         acc[mt][nt][3] + bi8);
            }
        }
        return;
    }

#pragma unroll
    for (int mt = 0; mt < 4; mt++) {
#pragma unroll
        for (int nt = 0; nt < 8; nt++) {
            int c = ocol + nt * 8;
            float2 bi = *(const float2*)(bias + c);
            float v0 = acc[mt][nt][0] + bi.x;
            float v1 = acc[mt][nt][1] + bi.y;
            float v2 = acc[mt][nt][2] + bi.x;
            float v3 = acc[mt][nt][3] + bi.y;
            if (doRelu) {
                v0 = fmaxf(v0, 0.f); v1 = fmaxf(v1, 0.f);
                v2 = fmaxf(v2, 0.f); v3 = fmaxf(v3, 0.f);
            }
            if (c < qcols) {
                v0 *= QSCALE; v1 *= QSCALE; v2 *= QSCALE; v3 *= QSCALE;
            }
            int r = orow + mt * 16;
            *(__half2*)(Ch + (size_t)r * N + c)       = __floats2half2_rn(v0, v1);
            *(__half2*)(Ch + (size_t)(r + 8) * N + c) = __floats2half2_rn(v2, v3);
        }
    }
}

// ================= tensorized flash attention (3-stage pipeline, log2 softmax, ones-col l) =================
// 128 q-rows/CTA, 256 thr. SMEM: Q[128] + 3x K[64] + 3x Vt[80] rows of 144B = 80640 B.
#define AROWB 144
#define AQTILE (128 * AROWB)            // 18432
#define AKTILE (64 * AROWB)             // 9216
#define AVTILE (80 * AROWB)             // 11520
#define ATT_SMEM (AQTILE + 3 * AKTILE + 3 * AVTILE)   // 80640

__global__ void __launch_bounds__(256) attn_kernel(
    const __half* __restrict__ qkh, const __half* __restrict__ vt,
    __half* __restrict__ att)
{
    extern __shared__ char sma[];
    uint32_t sb = smem_u32(sma);
    const uint32_t Qs = sb;
    const uint32_t Ks = sb + AQTILE;
    const uint32_t Vs = sb + AQTILE + 3 * AKTILE;
    char* VsP = sma + AQTILE + 3 * AKTILE;

    int tid = threadIdx.x, wid = tid >> 5, lane = tid & 31;
    int bh = blockIdx.y;
    int b = bh >> 4, h = bh & 15;
    int q0 = blockIdx.x << 7;
    int lr = lane & 15;
    int lk = (lane >> 4) << 4;

    const char* qbase = (const char*)(qkh + ((size_t)(b * 1024 + q0)) * QK_N + h * 64);
    const char* kbase = (const char*)(qkh + ((size_t)(b * 1024)) * QK_N + 1024 + h * 64);
    const char* vbase = (const char*)(vt + ((size_t)bh * 64) * 1024);

    // constant Vt rows 64-79 for ALL 3 buffers: row 64 = 1.0h (l column), 65-79 zero
    for (int idx = tid; idx < 3 * 16 * 9; idx += 256) {
        int buf = idx / 144;
        int rem = idx - buf * 144;
        int rrow = rem / 9, chk = rem - rrow * 9;
        uint32_t w = (rrow == 0) ? 0x3C003C00u : 0u;
        *(uint4*)(VsP + buf * AVTILE + (64 + rrow) * AROWB + chk * 16) =
            make_uint4(w, w, w, w);
    }

    // group 0: Q + K0,V0 ; group 1: K1,V1
#pragma unroll
    for (int g = 0; g < 4; g++) {
        int c = tid + (g << 8);
        int r = c >> 3, ch = (c & 7) << 4;
        cp16(Qs + r * AROWB + ch, qbase + (size_t)r * (QK_N * 2) + ch);
    }
#pragma unroll
    for (int g = 0; g < 2; g++) {
        int c = tid + (g << 8);
        int r = c >> 3, ch = (c & 7) << 4;
        cp16(Ks + r * AROWB + ch, kbase + (size_t)r * (QK_N * 2) + ch);
        cp16(Vs + r * AROWB + ch, vbase + (size_t)r * 2048 + ch);
    }
    CP_COMMIT();
#pragma unroll
    for (int g = 0; g < 2; g++) {
        int c = tid + (g << 8);
        int r = c >> 3, ch = (c & 7) << 4;
        cp16(Ks + AKTILE + r * AROWB + ch, kbase + (size_t)(64 + r) * (QK_N * 2) + ch);
        cp16(Vs + AVTILE + r * AROWB + ch, vbase + (size_t)r * 2048 + 128 + ch);
    }
    CP_COMMIT();

    CP_WAIT(1);
    __syncthreads();

    uint32_t Qf[4][4];
    {
        uint32_t qa = Qs + (wid * 16 + lr) * AROWB + lk;
#pragma unroll
        for (int kk = 0; kk < 4; kk++) LDM4(Qf[kk], qa + kk * 32);
    }

    float Oacc[9][4];
#pragma unroll
    for (int n = 0; n < 9; n++)
#pragma unroll
        for (int r = 0; r < 4; r++) Oacc[n][r] = 0.f;
    float m0 = -1e30f, m1 = -1e30f;

    for (int t = 0; t < 16; t++) {
        if (t < 15) { CP_WAIT(1); } else { CP_WAIT(0); }
        __syncthreads();

        // prefetch tile t+2 into buffer (t+2)%3 (safe: all warps past tile t-1)
        if (t + 2 < 16) {
            int nb = (t + 2) % 3;
#pragma unroll
            for (int g = 0; g < 2; g++) {
                int c = tid + (g << 8);
                int r = c >> 3, ch = (c & 7) << 4;
                cp16(Ks + nb * AKTILE + r * AROWB + ch,
                     kbase + (size_t)((t + 2) * 64 + r) * (QK_N * 2) + ch);
                cp16(Vs + nb * AVTILE + r * AROWB + ch,
                     vbase + (size_t)r * 2048 + (t + 2) * 128 + ch);
            }
            CP_COMMIT();
        }

        int cb = t % 3;
        uint32_t ck = cb * AKTILE;
        uint32_t cv = cb * AVTILE;

        // S = Q @ K^T  (log2-domain)
        float Sacc[8][4];
#pragma unroll
        for (int n = 0; n < 8; n++)
#pragma unroll
            for (int r = 0; r < 4; r++) Sacc[n][r] = 0.f;
        {
            uint32_t kb = Ks + ck + lr * AROWB + lk;
#pragma unroll
            for (int nn = 0; nn < 4; nn++) {
#pragma unroll
                for (int kk = 0; kk < 4; kk++) {
                    uint32_t kf[4];
                    LDM4(kf, kb + nn * 16 * AROWB + kk * 32);
                    mma16816(Sacc[2 * nn],     Qf[kk], kf[0], kf[2]);
                    mma16816(Sacc[2 * nn + 1], Qf[kk], kf[1], kf[3]);
                }
            }
        }

        float mx0 = -1e30f, mx1 = -1e30f;
#pragma unroll
        for (int n = 0; n < 8; n++) {
            mx0 = fmaxf(mx0, fmaxf(Sacc[n][0], Sacc[n][1]));
            mx1 = fmaxf(mx1, fmaxf(Sacc[n][2], Sacc[n][3]));
        }
        mx0 = fmaxf(mx0, __shfl_xor_sync(0xffffffffu, mx0, 1));
        mx0 = fmaxf(mx0, __shfl_xor_sync(0xffffffffu, mx0, 2));
        mx1 = fmaxf(mx1, __shfl_xor_sync(0xffffffffu, mx1, 1));
        mx1 = fmaxf(mx1, __shfl_xor_sync(0xffffffffu, mx1, 2));
        float nm0 = fmaxf(m0, mx0), nm1 = fmaxf(m1, mx1);
        float a0 = exp2f(m0 - nm0), a1 = exp2f(m1 - nm1);
        m0 = nm0; m1 = nm1;
#pragma unroll
        for (int n = 0; n < 9; n++) {
            Oacc[n][0] *= a0; Oacc[n][1] *= a0;
            Oacc[n][2] *= a1; Oacc[n][3] *= a1;
        }

        uint32_t Pa[4][4];
#pragma unroll
        for (int kk = 0; kk < 4; kk++) {
            Pa[kk][0] = ex2_h2(pack_h2(Sacc[2 * kk][0] - nm0,     Sacc[2 * kk][1] - nm0));
            Pa[kk][1] = ex2_h2(pack_h2(Sacc[2 * kk][2] - nm1,     Sacc[2 * kk][3] - nm1));
            Pa[kk][2] = ex2_h2(pack_h2(Sacc[2 * kk + 1][0] - nm0, Sacc[2 * kk + 1][1] - nm0));
            Pa[kk][3] = ex2_h2(pack_h2(Sacc[2 * kk + 1][2] - nm1, Sacc[2 * kk + 1][3] - nm1));
        }

        {
            uint32_t vb = Vs + cv + lr * AROWB + lk;
#pragma unroll
            for (int kk = 0; kk < 4; kk++) {
#pragma unroll
                for (int nn = 0; nn < 4; nn++) {
                    uint32_t vf[4];
                    LDM4(vf, vb + nn * 16 * AROWB + kk * 32);
                    mma16816(Oacc[2 * nn],     Pa[kk], vf[0], vf[2]);
                    mma16816(Oacc[2 * nn + 1], Pa[kk], vf[1], vf[3]);
                }
                uint32_t lf[4];
                LDM4(lf, vb + 64 * AROWB + kk * 32);
                mma16816(Oacc[8], Pa[kk], lf[0], lf[2]);
            }
        }
    }

    float lv0 = __shfl_sync(0xffffffffu, Oacc[8][0], lane & 28);
    float lv1 = __shfl_sync(0xffffffffu, Oacc[8][2], lane & 28);
    float invl0 = 1.f / lv0, invl1 = 1.f / lv1;
    int row = b * 1024 + q0 + wid * 16 + (lane >> 2);
    int col = h * 64 + ((lane & 3) << 1);
#pragma unroll
    for (int n = 0; n < 8; n++) {
        *(__half2*)(att + (size_t)row * 1024 + col + n * 8) =
            __floats2half2_rn(Oacc[n][0] * invl0, Oacc[n][1] * invl0);
        *(__half2*)(att + (size_t)(row + 8) * 1024 + col + n * 8) =
            __floats2half2_rn(Oacc[n][2] * invl1, Oacc[n][3] * invl1);
    }
}

// ================= warp-per-row residual + LayerNorm (row = 1024) =================
// residual 'a': f32 (af) or fp16 (ah) — whichever is non-null. b always fp16.
__global__ void __launch_bounds__(256) add_ln_kernel(
    const float* __restrict__ af, const __half* __restrict__ ah,
    const __half* __restrict__ b,
    const float* __restrict__ gamma, const float* __restrict__ beta,
    float* __restrict__ out, __half* __restrict__ oh)
{
    int warp = threadIdx.x >> 5, lane = threadIdx.x & 31;
    int row = (blockIdx.x << 3) + warp;
    size_t base = (size_t)row * 1024;

    float v[32];
    float s = 0.f, ss = 0.f;
#pragma unroll
    for (int i = 0; i < 8; i++) {
        int c = i * 128 + lane * 4;
        float a0, a1, a2, a3;
        if (af) {
            float4 va = *(const float4*)(af + base + c);
            a0 = va.x; a1 = va.y; a2 = va.z; a3 = va.w;
        } else {
            uint2 hv = *(const uint2*)(ah + base + c);
            float2 f0 = __half22float2(*(__half2*)&hv.x);
            float2 f1 = __half22float2(*(__half2*)&hv.y);
            a0 = f0.x; a1 = f0.y; a2 = f1.x; a3 = f1.y;
        }
        uint2 hb = *(const uint2*)(b + base + c);
        float2 g0 = __half22float2(*(__half2*)&hb.x);
        float2 g1 = __half22float2(*(__half2*)&hb.y);
        float x0 = a0 + g0.x, x1 = a1 + g0.y;
        float x2 = a2 + g1.x, x3 = a3 + g1.y;
        v[4 * i] = x0; v[4 * i + 1] = x1; v[4 * i + 2] = x2; v[4 * i + 3] = x3;
        s  += x0 + x1 + x2 + x3;
        ss += x0 * x0 + x1 * x1 + x2 * x2 + x3 * x3;
    }
#pragma unroll
    for (int o = 16; o > 0; o >>= 1) {
        s  += __shfl_xor_sync(0xffffffffu, s, o);
        ss += __shfl_xor_sync(0xffffffffu, ss, o);
    }
    float mean = s * (1.f / 1024.f);
    float var  = ss * (1.f / 1024.f) - mean * mean;
    float rstd = rsqrtf(var + 1e-5f);

#pragma unroll
    for (int i = 0; i < 8; i++) {
        int c = i * 128 + lane * 4;
        float4 g4  = *(const float4*)(gamma + c);
        float4 be4 = *(const float4*)(beta  + c);
        float o0 = (v[4 * i]     - mean) * rstd * g4.x + be4.x;
        float o1 = (v[4 * i + 1] - mean) * rstd * g4.y + be4.y;
        float o2 = (v[4 * i + 2] - mean) * rstd * g4.z + be4.z;
        float o3 = (v[4 * i + 3] - mean) * rstd * g4.w + be4.w;
        if (out) *(float4*)(out + base + c) = make_float4(o0, o1, o2, o3);
        if (oh) {
            *(__half2*)(oh + base + c)     = __floats2half2_rn(o0, o1);
            *(__half2*)(oh + base + c + 2) = __floats2half2_rn(o2, o3);
        }
    }
}

// ================= launch =================
extern "C" void kernel_launch(void* const* d_in, const int* in_sizes, int n_in,
                              void* d_out, int out_size)
{
    const float* src = (const float*)d_in[0];
    const float* Wq  = (const float*)d_in[1];
    const float* bq  = (const float*)d_in[2];
    const float* Wk  = (const float*)d_in[3];
    const float* bk  = (const float*)d_in[4];
    const float* Wv  = (const float*)d_in[5];
    const float* bv  = (const float*)d_in[6];
    const float* Wo  = (const float*)d_in[7];
    const float* bo  = (const float*)d_in[8];
    const float* g1  = (const float*)d_in[9];
    const float* be1 = (const float*)d_in[10];
    const float* W1  = (const float*)d_in[11];
    const float* b1  = (const float*)d_in[12];
    const float* W2  = (const float*)d_in[13];
    const float* b2  = (const float*)d_in[14];
    const float* g2  = (const float*)d_in[15];
    const float* be2 = (const float*)d_in[16];
    float* out = (float*)d_out;

    float* bqkv;
    __half *sh, *qkh, *vtp, *ath, *projh, *xh, *fhh, *ffh2, *Bq, *Bo, *B1, *B2;
    cudaGetSymbolAddress((void**)&bqkv,  g_bqkv);
    cudaGetSymbolAddress((void**)&sh,    g_src_h);
    cudaGetSymbolAddress((void**)&qkh,   g_qkh);
    cudaGetSymbolAddress((void**)&vtp,   g_vt);
    cudaGetSymbolAddress((void**)&ath,   g_att_h);
    cudaGetSymbolAddress((void**)&projh, g_proj_h);
    cudaGetSymbolAddress((void**)&xh,    g_x_h);
    cudaGetSymbolAddress((void**)&fhh,   g_ffh_h);
    cudaGetSymbolAddress((void**)&ffh2,  g_ff_h);
    cudaGetSymbolAddress((void**)&Bq, g_Bqkv);
    cudaGetSymbolAddress((void**)&Bo, g_Bo);
    cudaGetSymbolAddress((void**)&B1, g_B1);
    cudaGetSymbolAddress((void**)&B2, g_B2);

    cudaFuncSetAttribute(attn_kernel, cudaFuncAttributeMaxDynamicSharedMemorySize, ATT_SMEM);
    cudaFuncSetAttribute(mma_gemm_kernel, cudaFuncAttributeMaxDynamicSharedMemorySize, GEMM_SMEM);

    dim3 tb(32, 8);
    // 0. fused pre-pass
    prepass_kernel<<<PREPASS_BLOCKS, tb>>>(src, Wq, Wk, Wv, Wo, W1, W2, bq, bk, bv,
                                           sh, Bq, Bo, B1, B2);
    // 1a. QK projection -> fp16 qk (q section pre-scaled)
    mma_gemm_kernel<<<dim3(QK_N / 128, MROWS / 128), 128, GEMM_SMEM>>>(
        sh, Bq, bqkv, qkh, QK_N, D_, 0, 1024, 0);
    // 1b. V^T GEMM: A = Wv^T rows (Bq+2048*1024), B = src_h; scatter into vt
    mma_gemm_kernel<<<dim3(MROWS / 128, D_ / 128), 128, GEMM_SMEM>>>(
        Bq + 2048 * 1024, sh, bqkv + 2048, vtp, MROWS, D_, 0, 0, 1);
    // 2. tensorized attention -> att fp16
    attn_kernel<<<dim3(S_ / 128, B_ * H_), 256, ATT_SMEM>>>(qkh, vtp, ath);
    // 3. output projection -> proj fp16
    mma_gemm_kernel<<<dim3(D_ / 128, MROWS / 128), 128, GEMM_SMEM>>>(
        ath, Bo, bo, projh, D_, D_, 0, 0, 0);
    // 4. x = LN(src + proj) -> fp16 xh only
    add_ln_kernel<<<MROWS / 8, 256>>>(src, nullptr, projh, g1, be1, nullptr, xh);
    // 5. hidden = relu(x @ W1 + b1) -> fp16
    mma_gemm_kernel<<<dim3(F_ / 128, MROWS / 128), 128, GEMM_SMEM>>>(
        xh, B1, b1, fhh, F_, D_, 1, 0, 0);
    // 6. ff = hidden @ W2 + b2 -> fp16
    mma_gemm_kernel<<<dim3(D_ / 128, MROWS / 128), 128, GEMM_SMEM>>>(
        fhh, B2, b2, ffh2, D_, F_, 0, 0, 0);
    // 7. out = LN(x + ff) -> f32 d_out
    add_ln_kernel<<<MROWS / 8, 256>>>(nullptr, xh, ffh2, g2, be2, out, nullptr);
}

// round 16
// speedup vs baseline: 1.0076x; 1.0076x over previous
#include <cuda_runtime.h>
#include <cuda_fp16.h>
#include <cstdint>
#include <math.h>

// Shapes (fixed)
#define B_ 8
#define S_ 1024
#define D_ 1024
#define H_ 16
#define DK_ 64
#define F_ 4096
#define MROWS (B_ * S_)          // 8192
#define QKV_N (3 * D_)           // 3072
#define QK_N 2048

#define QSCALE 0.18033688f       // 0.125 * log2(e), folded into q

// ================= scratch (device globals; no allocations allowed) =================
__device__ float g_bqkv[QKV_N];
// fp16 activations
__device__ __half g_src_h [MROWS * D_];
__device__ __half g_qkh   [MROWS * QK_N];        // q|k fp16, head-major per section
__device__ __half g_vt    [B_ * H_ * DK_ * S_];  // V^T per (b,h): [dk][s]
__device__ __half g_att_h [MROWS * D_];
__device__ __half g_proj_h[MROWS * D_];
__device__ __half g_x_h   [MROWS * D_];
__device__ __half g_ffh_h [MROWS * F_];
__device__ __half g_ff_h  [MROWS * D_];
// pre-transposed fp16 weights, [N][K] row-major (B operands)
__device__ __half g_Bqkv[QKV_N * D_];
__device__ __half g_Bo  [D_ * D_];
__device__ __half g_B1  [F_ * D_];
__device__ __half g_B2  [D_ * F_];

// ================= helpers =================
__device__ __forceinline__ uint32_t smem_u32(const void* p) {
    uint32_t a;
    asm("{ .reg .u64 t; cvta.to.shared.u64 t, %1; cvt.u32.u64 %0, t; }" : "=r"(a) : "l"(p));
    return a;
}
__device__ __forceinline__ void cp16(uint32_t s, const void* g) {
    asm volatile("cp.async.cg.shared.global [%0], [%1], 16;" :: "r"(s), "l"(g));
}
#define CP_COMMIT() asm volatile("cp.async.commit_group;" ::: "memory")
#define CP_WAIT(n)  asm volatile("cp.async.wait_group %0;" :: "n"(n) : "memory")

#define LDM4(r, a) \
    asm volatile("ldmatrix.sync.aligned.m8n8.x4.shared.b16 {%0,%1,%2,%3}, [%4];" \
        : "=r"((r)[0]), "=r"((r)[1]), "=r"((r)[2]), "=r"((r)[3]) : "r"(a))

__device__ __forceinline__ void mma16816(float* c, const uint32_t* a, uint32_t b0, uint32_t b1) {
    asm volatile("mma.sync.aligned.m16n8k16.row.col.f32.f16.f16.f32 "
                 "{%0,%1,%2,%3}, {%4,%5,%6,%7}, {%8,%9}, {%0,%1,%2,%3};"
                 : "+f"(c[0]), "+f"(c[1]), "+f"(c[2]), "+f"(c[3])
                 : "r"(a[0]), "r"(a[1]), "r"(a[2]), "r"(a[3]), "r"(b0), "r"(b1));
}
__device__ __forceinline__ uint32_t pack_h2(float x, float y) {
    __half2 h = __floats2half2_rn(x, y);
    return *(uint32_t*)&h;
}
__device__ __forceinline__ uint32_t ex2_h2(uint32_t x) {
    uint32_t d;
    asm("ex2.approx.f16x2 %0, %1;" : "=r"(d) : "r"(x));
    return d;
}

// ================= fused pre-pass: all weight transposes + src fp16 + bias pack =================
__global__ void __launch_bounds__(256) prepass_kernel(
    const float* __restrict__ src,
    const float* __restrict__ Wq, const float* __restrict__ Wk, const float* __restrict__ Wv,
    const float* __restrict__ Wo, const float* __restrict__ W1, const float* __restrict__ W2,
    const float* __restrict__ bq, const float* __restrict__ bk, const float* __restrict__ bv,
    __half* __restrict__ sh, __half* __restrict__ Bq_, __half* __restrict__ Bo_,
    __half* __restrict__ B1_, __half* __restrict__ B2_)
{
    __shared__ float t[32][33];
    int x = threadIdx.x, y = threadIdx.y;
    int bid = blockIdx.x;

    const float* in; __half* oh;
    int C, opitch, r0, c0, orow0;

    if (bid < 3072) {                     // Wq/Wk/Wv: [H,1024,64] -> Bq rows sec*1024+h*64+dk
        int seg = bid >> 10;
        int local = bid & 1023;
        int bx = local & 1;
        int by = (local >> 1) & 31;
        int bz = local >> 6;
        const float* W = (seg == 0) ? Wq : (seg == 1) ? Wk : Wv;
        in = W + (size_t)bz * (1024 * 64);
        C = 64; oh = Bq_; opitch = 1024;
        r0 = by * 32; c0 = bx * 32;
        orow0 = seg * 1024 + bz * 64 + c0;
    } else if (bid < 4096) {              // Wo [1024,1024]
        int local = bid - 3072;
        int bx = local & 31, by = local >> 5;
        in = Wo; C = 1024; oh = Bo_; opitch = 1024;
        r0 = by * 32; c0 = bx * 32; orow0 = c0;
    } else if (bid < 8192) {              // W1 [1024,4096]
        int local = bid - 4096;
        int bx = local & 127, by = local >> 7;
        in = W1; C = 4096; oh = B1_; opitch = 1024;
        r0 = by * 32; c0 = bx * 32; orow0 = c0;
    } else if (bid < 12288) {             // W2 [4096,1024]
        int local = bid - 8192;
        int bx = local & 31, by = local >> 5;
        in = W2; C = 1024; oh = B2_; opitch = 4096;
        r0 = by * 32; c0 = bx * 32; orow0 = c0;
    } else if (bid < 20480) {             // src f32 -> fp16
        int local = bid - 12288;
        int tid = y * 32 + x;
        size_t i = ((size_t)local * 256 + tid) << 2;
        float4 v = *(const float4*)(src + i);
        *(__half2*)(sh + i)     = __floats2half2_rn(v.x, v.y);
        *(__half2*)(sh + i + 2) = __floats2half2_rn(v.z, v.w);
        return;
    } else {                              // bias pack
        int local = bid - 20480;
        int tid = y * 32 + x;
        int n = local * 256 + tid;
        if (n < QKV_N) {
            int sec = n >> 10, r = n & 1023;
            const float* bb = (sec == 0) ? bq : (sec == 1) ? bk : bv;
            g_bqkv[n] = bb[r];
        }
        return;
    }

#pragma unroll
    for (int i = 0; i < 4; i++)
        t[y + i * 8][x] = in[(size_t)(r0 + y + i * 8) * C + c0 + x];
    __syncthreads();
#pragma unroll
    for (int i = 0; i < 4; i++)
        oh[(size_t)(orow0 + y + i * 8) * opitch + r0 + x] = __float2half_rn(t[x][y + i * 8]);
}
#define PREPASS_BLOCKS 20492

// ================= shared GEMM tile body (128x128, 128 thr, 64x64 warp tile) =================
#define ROWB 144
#define HALF_STAGE (128 * ROWB)
#define STAGE_B (2 * HALF_STAGE)
#define GEMM_SMEM (2 * STAGE_B)

__device__ __forceinline__ void gload(uint32_t sb,
    const __half* __restrict__ A, const __half* __restrict__ Bw,
    int K, int k0, int tid)
{
#pragma unroll
    for (int g = 0; g < 16; g++) {
        int item = tid + (g << 7);
        int r = item >> 3;
        int ch = (item & 7) << 4;
        if (r < 128)
            cp16(sb + r * ROWB + ch, A + (size_t)r * K + k0 + (ch >> 1));
        else
            cp16(sb + HALF_STAGE + (r - 128) * ROWB + ch,
                 Bw + (size_t)(r - 128) * K + k0 + (ch >> 1));
    }
}

__device__ __forceinline__ void gemm_tile(
    const __half* __restrict__ A, const __half* __restrict__ Bw,
    const float* __restrict__ bias, __half* __restrict__ Ch,
    int N, int K, int doRelu, int qcols, int vtmode, int bm, int bn, uint32_t sb)
{
    int tid = threadIdx.x, wid = tid >> 5, lane = tid & 31;
    A  += (size_t)bm * K;
    Bw += (size_t)bn * K;

    float acc[4][8][4];
#pragma unroll
    for (int mt = 0; mt < 4; mt++)
#pragma unroll
        for (int nt = 0; nt < 8; nt++)
#pragma unroll
            for (int r = 0; r < 4; r++) acc[mt][nt][r] = 0.f;

    int wm = (wid >> 1) << 6;
    int wn = (wid & 1) << 6;
    int lr = lane & 15;
    int lk = (lane >> 4) << 4;

    int niter = K >> 6;
    gload(sb, A, Bw, K, 0, tid);
    CP_COMMIT();

    for (int it = 0; it < niter; it++) {
        if (it + 1 < niter) {
            gload(sb + ((it + 1) & 1) * STAGE_B, A, Bw, K, (it + 1) << 6, tid);
            CP_COMMIT();
            CP_WAIT(1);
        } else {
            CP_WAIT(0);
        }
        __syncthreads();

        uint32_t stage = sb + (it & 1) * STAGE_B;
        uint32_t ab = stage + (wm + lr) * ROWB + lk;
        uint32_t bb = stage + HALF_STAGE + (wn + lr) * ROWB + lk;
#pragma unroll
        for (int j = 0; j < 4; j++) {
            uint32_t ko = j << 5;
            uint32_t bf[4][4];
#pragma unroll
            for (int nb = 0; nb < 4; nb++)
                LDM4(bf[nb], bb + nb * 16 * ROWB + ko);
#pragma unroll
            for (int mt = 0; mt < 4; mt++) {
                uint32_t af[4];
                LDM4(af, ab + mt * 16 * ROWB + ko);
#pragma unroll
                for (int nb = 0; nb < 4; nb++) {
                    mma16816(acc[mt][2 * nb],     af, bf[nb][0], bf[nb][2]);
                    mma16816(acc[mt][2 * nb + 1], af, bf[nb][1], bf[nb][3]);
                }
            }
        }
        __syncthreads();
    }

    int orow = bm + wm + (lane >> 2);
    int ocol = bn + wn + ((lane & 3) << 1);

    if (vtmode) {
        // V^T scatter epilogue: bias per row; write vt[(b*16+h)*64+dk][s]
#pragma unroll
        for (int mt = 0; mt < 4; mt++) {
            int r0 = orow + mt * 16;
            float bi0 = bias[r0], bi8 = bias[r0 + 8];
            int h0 = r0 >> 6, dk0 = r0 & 63;
            int h8 = (r0 + 8) >> 6, dk8 = (r0 + 8) & 63;
#pragma unroll
            for (int nt = 0; nt < 8; nt++) {
                int c = ocol + nt * 8;
                int b = c >> 10, s = c & 1023;
                size_t o0 = ((size_t)((b * 16 + h0) * 64 + dk0)) * 1024 + s;
                size_t o8 = ((size_t)((b * 16 + h8) * 64 + dk8)) * 1024 + s;
                *(__half2*)(Ch + o0) = __floats2half2_rn(acc[mt][nt][0] + bi0,
                                                         acc[mt][nt][1] + bi0);
                *(__half2*)(Ch + o8) = __floats2half2_rn(acc[mt][nt][2] + bi8,
                                                         acc[mt][nt][3] + bi8);
            }
        }
        return;
    }

#pragma unroll
    for (int mt = 0; mt < 4; mt++) {
#pragma unroll
        for (int nt = 0; nt < 8; nt++) {
            int c = ocol + nt * 8;
            float2 bi = *(const float2*)(bias + c);
            float v0 = acc[mt][nt][0] + bi.x;
            float v1 = acc[mt][nt][1] + bi.y;
            float v2 = acc[mt][nt][2] + bi.x;
            float v3 = acc[mt][nt][3] + bi.y;
            if (doRelu) {
                v0 = fmaxf(v0, 0.f); v1 = fmaxf(v1, 0.f);
                v2 = fmaxf(v2, 0.f); v3 = fmaxf(v3, 0.f);
            }
            if (c < qcols) {
                v0 *= QSCALE; v1 *= QSCALE; v2 *= QSCALE; v3 *= QSCALE;
            }
            int r = orow + mt * 16;
            *(__half2*)(Ch + (size_t)r * N + c)       = __floats2half2_rn(v0, v1);
            *(__half2*)(Ch + (size_t)(r + 8) * N + c) = __floats2half2_rn(v2, v3);
        }
    }
}

// generic GEMM (proj / FFN)
__global__ void __launch_bounds__(128, 2) mma_gemm_kernel(
    const __half* __restrict__ A, const __half* __restrict__ Bw,
    const float* __restrict__ bias, __half* __restrict__ Ch,
    int N, int K, int doRelu)
{
    extern __shared__ char sm[];
    gemm_tile(A, Bw, bias, Ch, N, K, doRelu, 0, 0,
              blockIdx.y << 7, blockIdx.x << 7, smem_u32(sm));
}

// merged QK-projection + V^T GEMM: tiles 0..1023 = QK, 1024..1535 = VT
__global__ void __launch_bounds__(128, 2) qkvt_kernel(
    const __half* __restrict__ sh, const __half* __restrict__ Bq,
    const float* __restrict__ bqkv,
    __half* __restrict__ qkh, __half* __restrict__ vtp)
{
    extern __shared__ char sm[];
    uint32_t sb = smem_u32(sm);
    int bid = blockIdx.x;
    if (bid < 1024) {
        // QK: M=8192 (64 m-tiles), N=2048 (16 n-tiles); q cols pre-scaled
        gemm_tile(sh, Bq, bqkv, qkh, QK_N, D_, 0, 1024, 0,
                  (bid >> 4) << 7, (bid & 15) << 7, sb);
    } else {
        // VT: A = Wv^T rows, B = src_h; M=1024 (8 m-tiles), N=8192 (64 n-tiles)
        int v = bid - 1024;
        gemm_tile(Bq + 2048 * 1024, sh, bqkv + 2048, vtp, MROWS, D_, 0, 0, 1,
                  (v >> 6) << 7, (v & 63) << 7, sb);
    }
}

// ================= tensorized flash attention (2-stage, log2 softmax, ones-col l) =================
// 128 q-rows/CTA, 256 thr. SMEM: Q[128] + 2x K[64] + 2x Vt[80] rows of 144B = 59904 B.
#define AROWB 144
#define AQTILE (128 * AROWB)            // 18432
#define AKTILE (64 * AROWB)             // 9216
#define AVTILE (80 * AROWB)             // 11520
#define ATT_SMEM (AQTILE + 2 * AKTILE + 2 * AVTILE)   // 59904

__global__ void __launch_bounds__(256) attn_kernel(
    const __half* __restrict__ qkh, const __half* __restrict__ vt,
    __half* __restrict__ att)
{
    extern __shared__ char sma[];
    uint32_t sb = smem_u32(sma);
    const uint32_t Qs = sb;
    const uint32_t Ks = sb + AQTILE;
    const uint32_t Vs = sb + AQTILE + 2 * AKTILE;
    char* VsP = sma + AQTILE + 2 * AKTILE;

    int tid = threadIdx.x, wid = tid >> 5, lane = tid & 31;
    int bh = blockIdx.y;
    int b = bh >> 4, h = bh & 15;
    int q0 = blockIdx.x << 7;
    int lr = lane & 15;
    int lk = (lane >> 4) << 4;

    const char* qbase = (const char*)(qkh + ((size_t)(b * 1024 + q0)) * QK_N + h * 64);
    const char* kbase = (const char*)(qkh + ((size_t)(b * 1024)) * QK_N + 1024 + h * 64);
    const char* vbase = (const char*)(vt + ((size_t)bh * 64) * 1024);

    // constant Vt rows 64-79 for BOTH buffers: row 64 = 1.0h (l column), 65-79 zero
    for (int idx = tid; idx < 2 * 16 * 9; idx += 256) {
        int buf = idx / 144;
        int rem = idx - buf * 144;
        int rrow = rem / 9, chk = rem - rrow * 9;
        uint32_t w = (rrow == 0) ? 0x3C003C00u : 0u;
        *(uint4*)(VsP + buf * AVTILE + (64 + rrow) * AROWB + chk * 16) =
            make_uint4(w, w, w, w);
    }

    // load Q (128 rows) + tile 0 of K,Vt
#pragma unroll
    for (int g = 0; g < 4; g++) {
        int c = tid + (g << 8);
        int r = c >> 3, ch = (c & 7) << 4;
        cp16(Qs + r * AROWB + ch, qbase + (size_t)r * (QK_N * 2) + ch);
    }
#pragma unroll
    for (int g = 0; g < 2; g++) {
        int c = tid + (g << 8);
        int r = c >> 3, ch = (c & 7) << 4;
        cp16(Ks + r * AROWB + ch, kbase + (size_t)r * (QK_N * 2) + ch);
        cp16(Vs + r * AROWB + ch, vbase + (size_t)r * 2048 + ch);
    }
    CP_COMMIT();
    CP_WAIT(0);
    __syncthreads();

    uint32_t Qf[4][4];
    {
        uint32_t qa = Qs + (wid * 16 + lr) * AROWB + lk;
#pragma unroll
        for (int kk = 0; kk < 4; kk++) LDM4(Qf[kk], qa + kk * 32);
    }

    float Oacc[9][4];                    // n-tiles 0-7 = O, tile 8 col 64 = l
#pragma unroll
    for (int n = 0; n < 9; n++)
#pragma unroll
        for (int r = 0; r < 4; r++) Oacc[n][r] = 0.f;
    float m0 = -1e30f, m1 = -1e30f;

    for (int t = 0; t < 16; t++) {
        if (t + 1 < 16) {
            uint32_t nb = (t + 1) & 1;
#pragma unroll
            for (int g = 0; g < 2; g++) {
                int c = tid + (g << 8);
                int r = c >> 3, ch = (c & 7) << 4;
                cp16(Ks + nb * AKTILE + r * AROWB + ch,
                     kbase + (size_t)((t + 1) * 64 + r) * (QK_N * 2) + ch);
                cp16(Vs + nb * AVTILE + r * AROWB + ch,
                     vbase + (size_t)r * 2048 + (t + 1) * 128 + ch);
            }
            CP_COMMIT();
            CP_WAIT(1);
        } else {
            CP_WAIT(0);
        }
        __syncthreads();

        uint32_t ck = (t & 1) * AKTILE;
        uint32_t cv = (t & 1) * AVTILE;

        // S = Q @ K^T  (log2-domain)
        float Sacc[8][4];
#pragma unroll
        for (int n = 0; n < 8; n++)
#pragma unroll
            for (int r = 0; r < 4; r++) Sacc[n][r] = 0.f;
        {
            uint32_t kb = Ks + ck + lr * AROWB + lk;
#pragma unroll
            for (int nn = 0; nn < 4; nn++) {
#pragma unroll
                for (int kk = 0; kk < 4; kk++) {
                    uint32_t kf[4];
                    LDM4(kf, kb + nn * 16 * AROWB + kk * 32);
                    mma16816(Sacc[2 * nn],     Qf[kk], kf[0], kf[2]);
                    mma16816(Sacc[2 * nn + 1], Qf[kk], kf[1], kf[3]);
                }
            }
        }

        float mx0 = -1e30f, mx1 = -1e30f;
#pragma unroll
        for (int n = 0; n < 8; n++) {
            mx0 = fmaxf(mx0, fmaxf(Sacc[n][0], Sacc[n][1]));
            mx1 = fmaxf(mx1, fmaxf(Sacc[n][2], Sacc[n][3]));
        }
        mx0 = fmaxf(mx0, __shfl_xor_sync(0xffffffffu, mx0, 1));
        mx0 = fmaxf(mx0, __shfl_xor_sync(0xffffffffu, mx0, 2));
        mx1 = fmaxf(mx1, __shfl_xor_sync(0xffffffffu, mx1, 1));
        mx1 = fmaxf(mx1, __shfl_xor_sync(0xffffffffu, mx1, 2));
        float nm0 = fmaxf(m0, mx0), nm1 = fmaxf(m1, mx1);
        float a0 = exp2f(m0 - nm0), a1 = exp2f(m1 - nm1);
        m0 = nm0; m1 = nm1;
#pragma unroll
        for (int n = 0; n < 9; n++) {          // includes l column
            Oacc[n][0] *= a0; Oacc[n][1] *= a0;
            Oacc[n][2] *= a1; Oacc[n][3] *= a1;
        }

        uint32_t Pa[4][4];
#pragma unroll
        for (int kk = 0; kk < 4; kk++) {
            Pa[kk][0] = ex2_h2(pack_h2(Sacc[2 * kk][0] - nm0,     Sacc[2 * kk][1] - nm0));
            Pa[kk][1] = ex2_h2(pack_h2(Sacc[2 * kk][2] - nm1,     Sacc[2 * kk][3] - nm1));
            Pa[kk][2] = ex2_h2(pack_h2(Sacc[2 * kk + 1][0] - nm0, Sacc[2 * kk + 1][1] - nm0));
            Pa[kk][3] = ex2_h2(pack_h2(Sacc[2 * kk + 1][2] - nm1, Sacc[2 * kk + 1][3] - nm1));
        }

        {
            uint32_t vb = Vs + cv + lr * AROWB + lk;
#pragma unroll
            for (int kk = 0; kk < 4; kk++) {
#pragma unroll
                for (int nn = 0; nn < 4; nn++) {
                    uint32_t vf[4];
                    LDM4(vf, vb + nn * 16 * AROWB + kk * 32);
                    mma16816(Oacc[2 * nn],     Pa[kk], vf[0], vf[2]);
                    mma16816(Oacc[2 * nn + 1], Pa[kk], vf[1], vf[3]);
                }
                uint32_t lf[4];                     // ones row + zeros
                LDM4(lf, vb + 64 * AROWB + kk * 32);
                mma16816(Oacc[8], Pa[kk], lf[0], lf[2]);
            }
        }
        __syncthreads();
    }

    float lv0 = __shfl_sync(0xffffffffu, Oacc[8][0], lane & 28);
    float lv1 = __shfl_sync(0xffffffffu, Oacc[8][2], lane & 28);
    float invl0 = 1.f / lv0, invl1 = 1.f / lv1;
    int row = b * 1024 + q0 + wid * 16 + (lane >> 2);
    int col = h * 64 + ((lane & 3) << 1);
#pragma unroll
    for (int n = 0; n < 8; n++) {
        *(__half2*)(att + (size_t)row * 1024 + col + n * 8) =
            __floats2half2_rn(Oacc[n][0] * invl0, Oacc[n][1] * invl0);
        *(__half2*)(att + (size_t)(row + 8) * 1024 + col + n * 8) =
            __floats2half2_rn(Oacc[n][2] * invl1, Oacc[n][3] * invl1);
    }
}

// ================= warp-per-row residual + LayerNorm (row = 1024) =================
__global__ void __launch_bounds__(256) add_ln_kernel(
    const float* __restrict__ af, const __half* __restrict__ ah,
    const __half* __restrict__ b,
    const float* __restrict__ gamma, const float* __restrict__ beta,
    float* __restrict__ out, __half* __restrict__ oh)
{
    int warp = threadIdx.x >> 5, lane = threadIdx.x & 31;
    int row = (blockIdx.x << 3) + warp;
    size_t base = (size_t)row * 1024;

    float v[32];
    float s = 0.f, ss = 0.f;
#pragma unroll
    for (int i = 0; i < 8; i++) {
        int c = i * 128 + lane * 4;
        float a0, a1, a2, a3;
        if (af) {
            float4 va = *(const float4*)(af + base + c);
            a0 = va.x; a1 = va.y; a2 = va.z; a3 = va.w;
        } else {
            uint2 hv = *(const uint2*)(ah + base + c);
            float2 f0 = __half22float2(*(__half2*)&hv.x);
            float2 f1 = __half22float2(*(__half2*)&hv.y);
            a0 = f0.x; a1 = f0.y; a2 = f1.x; a3 = f1.y;
        }
        uint2 hb = *(const uint2*)(b + base + c);
        float2 g0 = __half22float2(*(__half2*)&hb.x);
        float2 g1 = __half22float2(*(__half2*)&hb.y);
        float x0 = a0 + g0.x, x1 = a1 + g0.y;
        float x2 = a2 + g1.x, x3 = a3 + g1.y;
        v[4 * i] = x0; v[4 * i + 1] = x1; v[4 * i + 2] = x2; v[4 * i + 3] = x3;
        s  += x0 + x1 + x2 + x3;
        ss += x0 * x0 + x1 * x1 + x2 * x2 + x3 * x3;
    }
#pragma unroll
    for (int o = 16; o > 0; o >>= 1) {
        s  += __shfl_xor_sync(0xffffffffu, s, o);
        ss += __shfl_xor_sync(0xffffffffu, ss, o);
    }
    float mean = s * (1.f / 1024.f);
    float var  = ss * (1.f / 1024.f) - mean * mean;
    float rstd = rsqrtf(var + 1e-5f);

#pragma unroll
    for (int i = 0; i < 8; i++) {
        int c = i * 128 + lane * 4;
        float4 g4  = *(const float4*)(gamma + c);
        float4 be4 = *(const float4*)(beta  + c);
        float o0 = (v[4 * i]     - mean) * rstd * g4.x + be4.x;
        float o1 = (v[4 * i + 1] - mean) * rstd * g4.y + be4.y;
        float o2 = (v[4 * i + 2] - mean) * rstd * g4.z + be4.z;
        float o3 = (v[4 * i + 3] - mean) * rstd * g4.w + be4.w;
        if (out) *(float4*)(out + base + c) = make_float4(o0, o1, o2, o3);
        if (oh) {
            *(__half2*)(oh + base + c)     = __floats2half2_rn(o0, o1);
            *(__half2*)(oh + base + c + 2) = __floats2half2_rn(o2, o3);
        }
    }
}

// ================= launch =================
extern "C" void kernel_launch(void* const* d_in, const int* in_sizes, int n_in,
                              void* d_out, int out_size)
{
    const float* src = (const float*)d_in[0];
    const float* Wq  = (const float*)d_in[1];
    const float* bq  = (const float*)d_in[2];
    const float* Wk  = (const float*)d_in[3];
    const float* bk  = (const float*)d_in[4];
    const float* Wv  = (const float*)d_in[5];
    const float* bv  = (const float*)d_in[6];
    const float* Wo  = (const float*)d_in[7];
    const float* bo  = (const float*)d_in[8];
    const float* g1  = (const float*)d_in[9];
    const float* be1 = (const float*)d_in[10];
    const float* W1  = (const float*)d_in[11];
    const float* b1  = (const float*)d_in[12];
    const float* W2  = (const float*)d_in[13];
    const float* b2  = (const float*)d_in[14];
    const float* g2  = (const float*)d_in[15];
    const float* be2 = (const float*)d_in[16];
    float* out = (float*)d_out;

    float* bqkv;
    __half *sh, *qkh, *vtp, *ath, *projh, *xh, *fhh, *ffh2, *Bq, *Bo, *B1, *B2;
    cudaGetSymbolAddress((void**)&bqkv,  g_bqkv);
    cudaGetSymbolAddress((void**)&sh,    g_src_h);
    cudaGetSymbolAddress((void**)&qkh,   g_qkh);
    cudaGetSymbolAddress((void**)&vtp,   g_vt);
    cudaGetSymbolAddress((void**)&ath,   g_att_h);
    cudaGetSymbolAddress((void**)&projh, g_proj_h);
    cudaGetSymbolAddress((void**)&xh,    g_x_h);
    cudaGetSymbolAddress((void**)&fhh,   g_ffh_h);
    cudaGetSymbolAddress((void**)&ffh2,  g_ff_h);
    cudaGetSymbolAddress((void**)&Bq, g_Bqkv);
    cudaGetSymbolAddress((void**)&Bo, g_Bo);
    cudaGetSymbolAddress((void**)&B1, g_B1);
    cudaGetSymbolAddress((void**)&B2, g_B2);

    cudaFuncSetAttribute(attn_kernel, cudaFuncAttributeMaxDynamicSharedMemorySize, ATT_SMEM);
    cudaFuncSetAttribute(mma_gemm_kernel, cudaFuncAttributeMaxDynamicSharedMemorySize, GEMM_SMEM);
    cudaFuncSetAttribute(qkvt_kernel, cudaFuncAttributeMaxDynamicSharedMemorySize, GEMM_SMEM);

    dim3 tb(32, 8);
    // 0. fused pre-pass
    prepass_kernel<<<PREPASS_BLOCKS, tb>>>(src, Wq, Wk, Wv, Wo, W1, W2, bq, bk, bv,
                                           sh, Bq, Bo, B1, B2);
    // 1. merged QK projection + V^T GEMM (one launch, 1536 tiles)
    qkvt_kernel<<<1536, 128, GEMM_SMEM>>>(sh, Bq, bqkv, qkh, vtp);
    // 2. tensorized attention -> att fp16
    attn_kernel<<<dim3(S_ / 128, B_ * H_), 256, ATT_SMEM>>>(qkh, vtp, ath);
    // 3. output projection -> proj fp16
    mma_gemm_kernel<<<dim3(D_ / 128, MROWS / 128), 128, GEMM_SMEM>>>(
        ath, Bo, bo, projh, D_, D_, 0);
    // 4. x = LN(src + proj) -> fp16 xh
    add_ln_kernel<<<MROWS / 8, 256>>>(src, nullptr, projh, g1, be1, nullptr, xh);
    // 5. hidden = relu(x @ W1 + b1) -> fp16
    mma_gemm_kernel<<<dim3(F_ / 128, MROWS / 128), 128, GEMM_SMEM>>>(
        xh, B1, b1, fhh, F_, D_, 1);
    // 6. ff = hidden @ W2 + b2 -> fp16
    mma_gemm_kernel<<<dim3(D_ / 128, MROWS / 128), 128, GEMM_SMEM>>>(
        fhh, B2, b2, ffh2, D_, F_, 0);
    // 7. out = LN(x + ff) -> f32 d_out
    add_ln_kernel<<<MROWS / 8, 256>>>(nullptr, xh, ffh2, g2, be2, out, nullptr);
}

// round 17
// speedup vs baseline: 1.0596x; 1.0516x over previous
#include <cuda_runtime.h>
#include <cuda_fp16.h>
#include <cstdint>
#include <math.h>

// Shapes (fixed)
#define B_ 8
#define S_ 1024
#define D_ 1024
#define H_ 16
#define DK_ 64
#define F_ 4096
#define MROWS (B_ * S_)          // 8192
#define QKV_N (3 * D_)           // 3072
#define QK_N 2048

#define QSCALE 0.18033688f       // 0.125 * log2(e), folded into q

// ================= scratch (device globals; no allocations allowed) =================
__device__ float g_bqkv[QKV_N];
// fp16 activations
__device__ __half g_src_h [MROWS * D_];
__device__ __half g_qkh   [MROWS * QK_N];        // q|k fp16, head-major per section
__device__ __half g_vt    [B_ * H_ * DK_ * S_];  // V^T per (b,h): [dk][s]
__device__ __half g_att_h [MROWS * D_];
__device__ __half g_proj_h[MROWS * D_];
__device__ __half g_x_h   [MROWS * D_];
__device__ __half g_ffh_h [MROWS * F_];
__device__ __half g_ff_h  [MROWS * D_];
// pre-transposed fp16 weights, [N][K] row-major (B operands)
__device__ __half g_Bqkv[QKV_N * D_];
__device__ __half g_Bo  [D_ * D_];
__device__ __half g_B1  [F_ * D_];
__device__ __half g_B2  [D_ * F_];

// ================= helpers =================
__device__ __forceinline__ uint32_t smem_u32(const void* p) {
    uint32_t a;
    asm("{ .reg .u64 t; cvta.to.shared.u64 t, %1; cvt.u32.u64 %0, t; }" : "=r"(a) : "l"(p));
    return a;
}
__device__ __forceinline__ void cp16(uint32_t s, const void* g) {
    asm volatile("cp.async.cg.shared.global [%0], [%1], 16;" :: "r"(s), "l"(g));
}
#define CP_COMMIT() asm volatile("cp.async.commit_group;" ::: "memory")
#define CP_WAIT(n)  asm volatile("cp.async.wait_group %0;" :: "n"(n) : "memory")

#define LDM4(r, a) \
    asm volatile("ldmatrix.sync.aligned.m8n8.x4.shared.b16 {%0,%1,%2,%3}, [%4];" \
        : "=r"((r)[0]), "=r"((r)[1]), "=r"((r)[2]), "=r"((r)[3]) : "r"(a))

__device__ __forceinline__ void mma16816(float* c, const uint32_t* a, uint32_t b0, uint32_t b1) {
    asm volatile("mma.sync.aligned.m16n8k16.row.col.f32.f16.f16.f32 "
                 "{%0,%1,%2,%3}, {%4,%5,%6,%7}, {%8,%9}, {%0,%1,%2,%3};"
                 : "+f"(c[0]), "+f"(c[1]), "+f"(c[2]), "+f"(c[3])
                 : "r"(a[0]), "r"(a[1]), "r"(a[2]), "r"(a[3]), "r"(b0), "r"(b1));
}
__device__ __forceinline__ uint32_t pack_h2(float x, float y) {
    __half2 h = __floats2half2_rn(x, y);
    return *(uint32_t*)&h;
}
__device__ __forceinline__ uint32_t ex2_h2(uint32_t x) {
    uint32_t d;
    asm("ex2.approx.f16x2 %0, %1;" : "=r"(d) : "r"(x));
    return d;
}

// ================= fused pre-pass: all weight transposes + src fp16 + bias pack =================
__global__ void __launch_bounds__(256) prepass_kernel(
    const float* __restrict__ src,
    const float* __restrict__ Wq, const float* __restrict__ Wk, const float* __restrict__ Wv,
    const float* __restrict__ Wo, const float* __restrict__ W1, const float* __restrict__ W2,
    const float* __restrict__ bq, const float* __restrict__ bk, const float* __restrict__ bv,
    __half* __restrict__ sh, __half* __restrict__ Bq_, __half* __restrict__ Bo_,
    __half* __restrict__ B1_, __half* __restrict__ B2_)
{
    __shared__ float t[32][33];
    int x = threadIdx.x, y = threadIdx.y;
    int bid = blockIdx.x;

    const float* in; __half* oh;
    int C, opitch, r0, c0, orow0;

    if (bid < 3072) {                     // Wq/Wk/Wv: [H,1024,64] -> Bq rows sec*1024+h*64+dk
        int seg = bid >> 10;
        int local = bid & 1023;
        int bx = local & 1;
        int by = (local >> 1) & 31;
        int bz = local >> 6;
        const float* W = (seg == 0) ? Wq : (seg == 1) ? Wk : Wv;
        in = W + (size_t)bz * (1024 * 64);
        C = 64; oh = Bq_; opitch = 1024;
        r0 = by * 32; c0 = bx * 32;
        orow0 = seg * 1024 + bz * 64 + c0;
    } else if (bid < 4096) {              // Wo [1024,1024]
        int local = bid - 3072;
        int bx = local & 31, by = local >> 5;
        in = Wo; C = 1024; oh = Bo_; opitch = 1024;
        r0 = by * 32; c0 = bx * 32; orow0 = c0;
    } else if (bid < 8192) {              // W1 [1024,4096]
        int local = bid - 4096;
        int bx = local & 127, by = local >> 7;
        in = W1; C = 4096; oh = B1_; opitch = 1024;
        r0 = by * 32; c0 = bx * 32; orow0 = c0;
    } else if (bid < 12288) {             // W2 [4096,1024]
        int local = bid - 8192;
        int bx = local & 31, by = local >> 5;
        in = W2; C = 1024; oh = B2_; opitch = 4096;
        r0 = by * 32; c0 = bx * 32; orow0 = c0;
    } else if (bid < 20480) {             // src f32 -> fp16
        int local = bid - 12288;
        int tid = y * 32 + x;
        size_t i = ((size_t)local * 256 + tid) << 2;
        float4 v = *(const float4*)(src + i);
        *(__half2*)(sh + i)     = __floats2half2_rn(v.x, v.y);
        *(__half2*)(sh + i + 2) = __floats2half2_rn(v.z, v.w);
        return;
    } else {                              // bias pack
        int local = bid - 20480;
        int tid = y * 32 + x;
        int n = local * 256 + tid;
        if (n < QKV_N) {
            int sec = n >> 10, r = n & 1023;
            const float* bb = (sec == 0) ? bq : (sec == 1) ? bk : bv;
            g_bqkv[n] = bb[r];
        }
        return;
    }

#pragma unroll
    for (int i = 0; i < 4; i++)
        t[y + i * 8][x] = in[(size_t)(r0 + y + i * 8) * C + c0 + x];
    __syncthreads();
#pragma unroll
    for (int i = 0; i < 4; i++)
        oh[(size_t)(orow0 + y + i * 8) * opitch + r0 + x] = __float2half_rn(t[x][y + i * 8]);
}
#define PREPASS_BLOCKS 20492

// ================= shared GEMM tile body (128x128 CTA, 256 thr, 32x64 warp tile) =================
// 8 warps: wm = (wid>>1)*32 (4 m-slots), wn = (wid&1)*64. acc 64 f32/thread -> 16 warps/SM.
#define ROWB 144
#define HALF_STAGE (128 * ROWB)
#define STAGE_B (2 * HALF_STAGE)
#define GEMM_SMEM (2 * STAGE_B)

__device__ __forceinline__ void gload(uint32_t sb,
    const __half* __restrict__ A, const __half* __restrict__ Bw,
    int K, int k0, int tid)
{
#pragma unroll
    for (int g = 0; g < 8; g++) {
        int item = tid + (g << 8);
        int r = item >> 3;                   // 0..255
        int ch = (item & 7) << 4;
        if (r < 128)
            cp16(sb + r * ROWB + ch, A + (size_t)r * K + k0 + (ch >> 1));
        else
            cp16(sb + HALF_STAGE + (r - 128) * ROWB + ch,
                 Bw + (size_t)(r - 128) * K + k0 + (ch >> 1));
    }
}

__device__ __forceinline__ void gemm_tile(
    const __half* __restrict__ A, const __half* __restrict__ Bw,
    const float* __restrict__ bias, __half* __restrict__ Ch,
    int N, int K, int doRelu, int qcols, int vtmode, int bm, int bn, uint32_t sb)
{
    int tid = threadIdx.x, wid = tid >> 5, lane = tid & 31;
    A  += (size_t)bm * K;
    Bw += (size_t)bn * K;

    float acc[2][8][4];
#pragma unroll
    for (int mt = 0; mt < 2; mt++)
#pragma unroll
        for (int nt = 0; nt < 8; nt++)
#pragma unroll
            for (int r = 0; r < 4; r++) acc[mt][nt][r] = 0.f;

    int wm = (wid >> 1) << 5;    // 0/32/64/96
    int wn = (wid & 1) << 6;     // 0/64
    int lr = lane & 15;
    int lk = (lane >> 4) << 4;

    int niter = K >> 6;
    gload(sb, A, Bw, K, 0, tid);
    CP_COMMIT();

    for (int it = 0; it < niter; it++) {
        if (it + 1 < niter) {
            gload(sb + ((it + 1) & 1) * STAGE_B, A, Bw, K, (it + 1) << 6, tid);
            CP_COMMIT();
            CP_WAIT(1);
        } else {
            CP_WAIT(0);
        }
        __syncthreads();

        uint32_t stage = sb + (it & 1) * STAGE_B;
        uint32_t ab = stage + (wm + lr) * ROWB + lk;
        uint32_t bb = stage + HALF_STAGE + (wn + lr) * ROWB + lk;
#pragma unroll
        for (int j = 0; j < 4; j++) {
            uint32_t ko = j << 5;
            uint32_t bf[4][4];
#pragma unroll
            for (int nb = 0; nb < 4; nb++)
                LDM4(bf[nb], bb + nb * 16 * ROWB + ko);
#pragma unroll
            for (int mt = 0; mt < 2; mt++) {
                uint32_t af[4];
                LDM4(af, ab + mt * 16 * ROWB + ko);
#pragma unroll
                for (int nb = 0; nb < 4; nb++) {
                    mma16816(acc[mt][2 * nb],     af, bf[nb][0], bf[nb][2]);
                    mma16816(acc[mt][2 * nb + 1], af, bf[nb][1], bf[nb][3]);
                }
            }
        }
        __syncthreads();
    }

    int orow = bm + wm + (lane >> 2);
    int ocol = bn + wn + ((lane & 3) << 1);

    if (vtmode) {
        // V^T scatter epilogue: bias per row; write vt[(b*16+h)*64+dk][s]
#pragma unroll
        for (int mt = 0; mt < 2; mt++) {
            int r0 = orow + mt * 16;
            float bi0 = bias[r0], bi8 = bias[r0 + 8];
            int h0 = r0 >> 6, dk0 = r0 & 63;
            int h8 = (r0 + 8) >> 6, dk8 = (r0 + 8) & 63;
#pragma unroll
            for (int nt = 0; nt < 8; nt++) {
                int c = ocol + nt * 8;
                int b = c >> 10, s = c & 1023;
                size_t o0 = ((size_t)((b * 16 + h0) * 64 + dk0)) * 1024 + s;
                size_t o8 = ((size_t)((b * 16 + h8) * 64 + dk8)) * 1024 + s;
                *(__half2*)(Ch + o0) = __floats2half2_rn(acc[mt][nt][0] + bi0,
                                                         acc[mt][nt][1] + bi0);
                *(__half2*)(Ch + o8) = __floats2half2_rn(acc[mt][nt][2] + bi8,
                                                         acc[mt][nt][3] + bi8);
            }
        }
        return;
    }

#pragma unroll
    for (int mt = 0; mt < 2; mt++) {
#pragma unroll
        for (int nt = 0; nt < 8; nt++) {
            int c = ocol + nt * 8;
            float2 bi = *(const float2*)(bias + c);
            float v0 = acc[mt][nt][0] + bi.x;
            float v1 = acc[mt][nt][1] + bi.y;
            float v2 = acc[mt][nt][2] + bi.x;
            float v3 = acc[mt][nt][3] + bi.y;
            if (doRelu) {
                v0 = fmaxf(v0, 0.f); v1 = fmaxf(v1, 0.f);
                v2 = fmaxf(v2, 0.f); v3 = fmaxf(v3, 0.f);
            }
            if (c < qcols) {
                v0 *= QSCALE; v1 *= QSCALE; v2 *= QSCALE; v3 *= QSCALE;
            }
            int r = orow + mt * 16;
            *(__half2*)(Ch + (size_t)r * N + c)       = __floats2half2_rn(v0, v1);
            *(__half2*)(Ch + (size_t)(r + 8) * N + c) = __floats2half2_rn(v2, v3);
        }
    }
}

// generic GEMM (proj / FFN)
__global__ void __launch_bounds__(256, 2) mma_gemm_kernel(
    const __half* __restrict__ A, const __half* __restrict__ Bw,
    const float* __restrict__ bias, __half* __restrict__ Ch,
    int N, int K, int doRelu)
{
    extern __shared__ char sm[];
    gemm_tile(A, Bw, bias, Ch, N, K, doRelu, 0, 0,
              blockIdx.y << 7, blockIdx.x << 7, smem_u32(sm));
}

// merged QK-projection + V^T GEMM: tiles 0..1023 = QK, 1024..1535 = VT
__global__ void __launch_bounds__(256, 2) qkvt_kernel(
    const __half* __restrict__ sh, const __half* __restrict__ Bq,
    const float* __restrict__ bqkv,
    __half* __restrict__ qkh, __half* __restrict__ vtp)
{
    extern __shared__ char sm[];
    uint32_t sb = smem_u32(sm);
    int bid = blockIdx.x;
    if (bid < 1024) {
        gemm_tile(sh, Bq, bqkv, qkh, QK_N, D_, 0, 1024, 0,
                  (bid >> 4) << 7, (bid & 15) << 7, sb);
    } else {
        int v = bid - 1024;
        gemm_tile(Bq + 2048 * 1024, sh, bqkv + 2048, vtp, MROWS, D_, 0, 0, 1,
                  (v >> 6) << 7, (v & 63) << 7, sb);
    }
}

// ================= tensorized flash attention (2-stage, log2 softmax, ones-col l) =================
#define AROWB 144
#define AQTILE (128 * AROWB)
#define AKTILE (64 * AROWB)
#define AVTILE (80 * AROWB)
#define ATT_SMEM (AQTILE + 2 * AKTILE + 2 * AVTILE)   // 59904

__global__ void __launch_bounds__(256) attn_kernel(
    const __half* __restrict__ qkh, const __half* __restrict__ vt,
    __half* __restrict__ att)
{
    extern __shared__ char sma[];
    uint32_t sb = smem_u32(sma);
    const uint32_t Qs = sb;
    const uint32_t Ks = sb + AQTILE;
    const uint32_t Vs = sb + AQTILE + 2 * AKTILE;
    char* VsP = sma + AQTILE + 2 * AKTILE;

    int tid = threadIdx.x, wid = tid >> 5, lane = tid & 31;
    int bh = blockIdx.y;
    int b = bh >> 4, h = bh & 15;
    int q0 = blockIdx.x << 7;
    int lr = lane & 15;
    int lk = (lane >> 4) << 4;

    const char* qbase = (const char*)(qkh + ((size_t)(b * 1024 + q0)) * QK_N + h * 64);
    const char* kbase = (const char*)(qkh + ((size_t)(b * 1024)) * QK_N + 1024 + h * 64);
    const char* vbase = (const char*)(vt + ((size_t)bh * 64) * 1024);

    for (int idx = tid; idx < 2 * 16 * 9; idx += 256) {
        int buf = idx / 144;
        int rem = idx - buf * 144;
        int rrow = rem / 9, chk = rem - rrow * 9;
        uint32_t w = (rrow == 0) ? 0x3C003C00u : 0u;
        *(uint4*)(VsP + buf * AVTILE + (64 + rrow) * AROWB + chk * 16) =
            make_uint4(w, w, w, w);
    }

#pragma unroll
    for (int g = 0; g < 4; g++) {
        int c = tid + (g << 8);
        int r = c >> 3, ch = (c & 7) << 4;
        cp16(Qs + r * AROWB + ch, qbase + (size_t)r * (QK_N * 2) + ch);
    }
#pragma unroll
    for (int g = 0; g < 2; g++) {
        int c = tid + (g << 8);
        int r = c >> 3, ch = (c & 7) << 4;
        cp16(Ks + r * AROWB + ch, kbase + (size_t)r * (QK_N * 2) + ch);
        cp16(Vs + r * AROWB + ch, vbase + (size_t)r * 2048 + ch);
    }
    CP_COMMIT();
    CP_WAIT(0);
    __syncthreads();

    uint32_t Qf[4][4];
    {
        uint32_t qa = Qs + (wid * 16 + lr) * AROWB + lk;
#pragma unroll
        for (int kk = 0; kk < 4; kk++) LDM4(Qf[kk], qa + kk * 32);
    }

    float Oacc[9][4];
#pragma unroll
    for (int n = 0; n < 9; n++)
#pragma unroll
        for (int r = 0; r < 4; r++) Oacc[n][r] = 0.f;
    float m0 = -1e30f, m1 = -1e30f;

    for (int t = 0; t < 16; t++) {
        if (t + 1 < 16) {
            uint32_t nb = (t + 1) & 1;
#pragma unroll
            for (int g = 0; g < 2; g++) {
                int c = tid + (g << 8);
                int r = c >> 3, ch = (c & 7) << 4;
                cp16(Ks + nb * AKTILE + r * AROWB + ch,
                     kbase + (size_t)((t + 1) * 64 + r) * (QK_N * 2) + ch);
                cp16(Vs + nb * AVTILE + r * AROWB + ch,
                     vbase + (size_t)r * 2048 + (t + 1) * 128 + ch);
            }
            CP_COMMIT();
            CP_WAIT(1);
        } else {
            CP_WAIT(0);
        }
        __syncthreads();

        uint32_t ck = (t & 1) * AKTILE;
        uint32_t cv = (t & 1) * AVTILE;

        float Sacc[8][4];
#pragma unroll
        for (int n = 0; n < 8; n++)
#pragma unroll
            for (int r = 0; r < 4; r++) Sacc[n][r] = 0.f;
        {
            uint32_t kb = Ks + ck + lr * AROWB + lk;
#pragma unroll
            for (int nn = 0; nn < 4; nn++) {
#pragma unroll
                for (int kk = 0; kk < 4; kk++) {
                    uint32_t kf[4];
                    LDM4(kf, kb + nn * 16 * AROWB + kk * 32);
                    mma16816(Sacc[2 * nn],     Qf[kk], kf[0], kf[2]);
                    mma16816(Sacc[2 * nn + 1], Qf[kk], kf[1], kf[3]);
                }
            }
        }

        float mx0 = -1e30f, mx1 = -1e30f;
#pragma unroll
        for (int n = 0; n < 8; n++) {
            mx0 = fmaxf(mx0, fmaxf(Sacc[n][0], Sacc[n][1]));
            mx1 = fmaxf(mx1, fmaxf(Sacc[n][2], Sacc[n][3]));
        }
        mx0 = fmaxf(mx0, __shfl_xor_sync(0xffffffffu, mx0, 1));
        mx0 = fmaxf(mx0, __shfl_xor_sync(0xffffffffu, mx0, 2));
        mx1 = fmaxf(mx1, __shfl_xor_sync(0xffffffffu, mx1, 1));
        mx1 = fmaxf(mx1, __shfl_xor_sync(0xffffffffu, mx1, 2));
        float nm0 = fmaxf(m0, mx0), nm1 = fmaxf(m1, mx1);
        float a0 = exp2f(m0 - nm0), a1 = exp2f(m1 - nm1);
        m0 = nm0; m1 = nm1;
#pragma unroll
        for (int n = 0; n < 9; n++) {
            Oacc[n][0] *= a0; Oacc[n][1] *= a0;
            Oacc[n][2] *= a1; Oacc[n][3] *= a1;
        }

        uint32_t Pa[4][4];
#pragma unroll
        for (int kk = 0; kk < 4; kk++) {
            Pa[kk][0] = ex2_h2(pack_h2(Sacc[2 * kk][0] - nm0,     Sacc[2 * kk][1] - nm0));
            Pa[kk][1] = ex2_h2(pack_h2(Sacc[2 * kk][2] - nm1,     Sacc[2 * kk][3] - nm1));
            Pa[kk][2] = ex2_h2(pack_h2(Sacc[2 * kk + 1][0] - nm0, Sacc[2 * kk + 1][1] - nm0));
            Pa[kk][3] = ex2_h2(pack_h2(Sacc[2 * kk + 1][2] - nm1, Sacc[2 * kk + 1][3] - nm1));
        }

        {
            uint32_t vb = Vs + cv + lr * AROWB + lk;
#pragma unroll
            for (int kk = 0; kk < 4; kk++) {
#pragma unroll
                for (int nn = 0; nn < 4; nn++) {
                    uint32_t vf[4];
                    LDM4(vf, vb + nn * 16 * AROWB + kk * 32);
                    mma16816(Oacc[2 * nn],     Pa[kk], vf[0], vf[2]);
                    mma16816(Oacc[2 * nn + 1], Pa[kk], vf[1], vf[3]);
                }
                uint32_t lf[4];
                LDM4(lf, vb + 64 * AROWB + kk * 32);
                mma16816(Oacc[8], Pa[kk], lf[0], lf[2]);
            }
        }
        __syncthreads();
    }

    float lv0 = __shfl_sync(0xffffffffu, Oacc[8][0], lane & 28);
    float lv1 = __shfl_sync(0xffffffffu, Oacc[8][2], lane & 28);
    float invl0 = 1.f / lv0, invl1 = 1.f / lv1;
    int row = b * 1024 + q0 + wid * 16 + (lane >> 2);
    int col = h * 64 + ((lane & 3) << 1);
#pragma unroll
    for (int n = 0; n < 8; n++) {
        *(__half2*)(att + (size_t)row * 1024 + col + n * 8) =
            __floats2half2_rn(Oacc[n][0] * invl0, Oacc[n][1] * invl0);
        *(__half2*)(att + (size_t)(row + 8) * 1024 + col + n * 8) =
            __floats2half2_rn(Oacc[n][2] * invl1, Oacc[n][3] * invl1);
    }
}

// ================= warp-per-row residual + LayerNorm (row = 1024) =================
__global__ void __launch_bounds__(256) add_ln_kernel(
    const float* __restrict__ af, const __half* __restrict__ ah,
    const __half* __restrict__ b,
    const float* __restrict__ gamma, const float* __restrict__ beta,
    float* __restrict__ out, __half* __restrict__ oh)
{
    int warp = threadIdx.x >> 5, lane = threadIdx.x & 31;
    int row = (blockIdx.x << 3) + warp;
    size_t base = (size_t)row * 1024;

    float v[32];
    float s = 0.f, ss = 0.f;
#pragma unroll
    for (int i = 0; i < 8; i++) {
        int c = i * 128 + lane * 4;
        float a0, a1, a2, a3;
        if (af) {
            float4 va = *(const float4*)(af + base + c);
            a0 = va.x; a1 = va.y; a2 = va.z; a3 = va.w;
        } else {
            uint2 hv = *(const uint2*)(ah + base + c);
            float2 f0 = __half22float2(*(__half2*)&hv.x);
            float2 f1 = __half22float2(*(__half2*)&hv.y);
            a0 = f0.x; a1 = f0.y; a2 = f1.x; a3 = f1.y;
        }
        uint2 hb = *(const uint2*)(b + base + c);
        float2 g0 = __half22float2(*(__half2*)&hb.x);
        float2 g1 = __half22float2(*(__half2*)&hb.y);
        float x0 = a0 + g0.x, x1 = a1 + g0.y;
        float x2 = a2 + g1.x, x3 = a3 + g1.y;
        v[4 * i] = x0; v[4 * i + 1] = x1; v[4 * i + 2] = x2; v[4 * i + 3] = x3;
        s  += x0 + x1 + x2 + x3;
        ss += x0 * x0 + x1 * x1 + x2 * x2 + x3 * x3;
    }
#pragma unroll
    for (int o = 16; o > 0; o >>= 1) {
        s  += __shfl_xor_sync(0xffffffffu, s, o);
        ss += __shfl_xor_sync(0xffffffffu, ss, o);
    }
    float mean = s * (1.f / 1024.f);
    float var  = ss * (1.f / 1024.f) - mean * mean;
    float rstd = rsqrtf(var + 1e-5f);

#pragma unroll
    for (int i = 0; i < 8; i++) {
        int c = i * 128 + lane * 4;
        float4 g4  = *(const float4*)(gamma + c);
        float4 be4 = *(const float4*)(beta  + c);
        float o0 = (v[4 * i]     - mean) * rstd * g4.x + be4.x;
        float o1 = (v[4 * i + 1] - mean) * rstd * g4.y + be4.y;
        float o2 = (v[4 * i + 2] - mean) * rstd * g4.z + be4.z;
        float o3 = (v[4 * i + 3] - mean) * rstd * g4.w + be4.w;
        if (out) *(float4*)(out + base + c) = make_float4(o0, o1, o2, o3);
        if (oh) {
            *(__half2*)(oh + base + c)     = __floats2half2_rn(o0, o1);
            *(__half2*)(oh + base + c + 2) = __floats2half2_rn(o2, o3);
        }
    }
}

// ================= launch =================
extern "C" void kernel_launch(void* const* d_in, const int* in_sizes, int n_in,
                              void* d_out, int out_size)
{
    const float* src = (const float*)d_in[0];
    const float* Wq  = (const float*)d_in[1];
    const float* bq  = (const float*)d_in[2];
    const float* Wk  = (const float*)d_in[3];
    const float* bk  = (const float*)d_in[4];
    const float* Wv  = (const float*)d_in[5];
    const float* bv  = (const float*)d_in[6];
    const float* Wo  = (const float*)d_in[7];
    const float* bo  = (const float*)d_in[8];
    const float* g1  = (const float*)d_in[9];
    const float* be1 = (const float*)d_in[10];
    const float* W1  = (const float*)d_in[11];
    const float* b1  = (const float*)d_in[12];
    const float* W2  = (const float*)d_in[13];
    const float* b2  = (const float*)d_in[14];
    const float* g2  = (const float*)d_in[15];
    const float* be2 = (const float*)d_in[16];
    float* out = (float*)d_out;

    float* bqkv;
    __half *sh, *qkh, *vtp, *ath, *projh, *xh, *fhh, *ffh2, *Bq, *Bo, *B1, *B2;
    cudaGetSymbolAddress((void**)&bqkv,  g_bqkv);
    cudaGetSymbolAddress((void**)&sh,    g_src_h);
    cudaGetSymbolAddress((void**)&qkh,   g_qkh);
    cudaGetSymbolAddress((void**)&vtp,   g_vt);
    cudaGetSymbolAddress((void**)&ath,   g_att_h);
    cudaGetSymbolAddress((void**)&projh, g_proj_h);
    cudaGetSymbolAddress((void**)&xh,    g_x_h);
    cudaGetSymbolAddress((void**)&fhh,   g_ffh_h);
    cudaGetSymbolAddress((void**)&ffh2,  g_ff_h);
    cudaGetSymbolAddress((void**)&Bq, g_Bqkv);
    cudaGetSymbolAddress((void**)&Bo, g_Bo);
    cudaGetSymbolAddress((void**)&B1, g_B1);
    cudaGetSymbolAddress((void**)&B2, g_B2);

    cudaFuncSetAttribute(attn_kernel, cudaFuncAttributeMaxDynamicSharedMemorySize, ATT_SMEM);
    cudaFuncSetAttribute(mma_gemm_kernel, cudaFuncAttributeMaxDynamicSharedMemorySize, GEMM_SMEM);
    cudaFuncSetAttribute(qkvt_kernel, cudaFuncAttributeMaxDynamicSharedMemorySize, GEMM_SMEM);

    dim3 tb(32, 8);
    // 0. fused pre-pass
    prepass_kernel<<<PREPASS_BLOCKS, tb>>>(src, Wq, Wk, Wv, Wo, W1, W2, bq, bk, bv,
                                           sh, Bq, Bo, B1, B2);
    // 1. merged QK projection + V^T GEMM (one launch, 1536 tiles)
    qkvt_kernel<<<1536, 256, GEMM_SMEM>>>(sh, Bq, bqkv, qkh, vtp);
    // 2. tensorized attention -> att fp16
    attn_kernel<<<dim3(S_ / 128, B_ * H_), 256, ATT_SMEM>>>(qkh, vtp, ath);
    // 3. output projection -> proj fp16
    mma_gemm_kernel<<<dim3(D_ / 128, MROWS / 128), 256, GEMM_SMEM>>>(
        ath, Bo, bo, projh, D_, D_, 0);
    // 4. x = LN(src_fp16 + proj) -> fp16 xh
    add_ln_kernel<<<MROWS / 8, 256>>>(nullptr, sh, projh, g1, be1, nullptr, xh);
    // 5. hidden = relu(x @ W1 + b1) -> fp16
    mma_gemm_kernel<<<dim3(F_ / 128, MROWS / 128), 256, GEMM_SMEM>>>(
        xh, B1, b1, fhh, F_, D_, 1);
    // 6. ff = hidden @ W2 + b2 -> fp16
    mma_gemm_kernel<<<dim3(D_ / 128, MROWS / 128), 256, GEMM_SMEM>>>(
        fhh, B2, b2, ffh2, D_, F_, 0);
    // 7. out = LN(x + ff) -> f32 d_out
    add_ln_kernel<<<MROWS / 8, 256>>>(nullptr, xh, ffh2, g2, be2, out, nullptr);
}